// round 1
// baseline (speedup 1.0000x reference)
#include <cuda_runtime.h>
#include <math.h>

#define Bn 64
#define Pn 64
#define Nn 1000
#define Hn 128
#define PT 16          // p-tile per block
#define PTB (Pn / PT)  // 4
#define KT 64          // n-chunk (k dim of masked GEMM)
#define S2 18          // padded row stride for [.,PT] transposed tiles (even -> 8B aligned pairs)
#define NT 64          // n-chunk for score GEMM
#define NT2 66         // padded stride for transposed E tile

// scratch: final_q [B,P,H]  (2 MB, static device global -> no allocation)
__device__ float g_fq[Bn * Pn * Hn];

// ---- f32x2 packed-FMA helpers (Blackwell-only pipe, ptxas never auto-emits) ----
__device__ __forceinline__ void ffma2(unsigned long long &d, unsigned long long a,
                                      unsigned long long b) {
    asm("fma.rn.f32x2 %0, %1, %2, %0;" : "+l"(d) : "l"(a), "l"(b));
}
__device__ __forceinline__ unsigned long long dup2(float x) {
    unsigned long long r;
    asm("mov.b64 %0, {%1, %1};" : "=l"(r) : "f"(x));
    return r;
}
__device__ __forceinline__ float2 unpk(unsigned long long v) {
    float2 f;
    asm("mov.b64 {%0, %1}, %2;" : "=f"(f.x), "=f"(f.y) : "l"(v));
    return f;
}

// =====================================================================
// Kernel 1: per (b, p-tile): masked aggregation GEMM + mean/q_graph +
//           3x HxH projections + load embedding  ->  g_fq
// =====================================================================
__global__ __launch_bounds__(128) void k_prep(
    const float* __restrict__ emb,    // [B,N,H]
    const float* __restrict__ encq1,  // [B,P,H]
    const int*   __restrict__ lastn,  // [B,P]
    const float* __restrict__ loadv,  // [B,P]
    const float* __restrict__ gmask,  // [B,P,N]
    const float* __restrict__ Wg, const float* __restrict__ Wf,
    const float* __restrict__ Wl, const float* __restrict__ Wv,
    const float* __restrict__ Wload, const float* __restrict__ bload)
{
    const int b  = blockIdx.x >> 2;
    const int p0 = (blockIdx.x & 3) * PT;
    const int tx = threadIdx.x;  // == h, 0..127

    __shared__ __align__(16) float Es[KT * Hn];      // 32 KB, reused later
    __shared__ __align__(16) float mt[KT][PT + 2];   // transposed mask chunk
    __shared__ float meanv[Hn];

    unsigned long long acc[8];
#pragma unroll
    for (int j = 0; j < 8; j++) acc[j] = 0ull;
    float csum = 0.f;

    for (int n0 = 0; n0 < Nn; n0 += KT) {
        const int kt = min(KT, Nn - n0);
        // stage E chunk (coalesced float4 copy)
        const float4* eb  = reinterpret_cast<const float4*>(emb + (size_t)(b * Nn + n0) * Hn);
        float4*       es4 = reinterpret_cast<float4*>(Es);
        for (int id = tx; id < kt * (Hn / 4); id += 128) es4[id] = eb[id];
        // stage mask chunk transposed, converting -inf -> 1.0
#pragma unroll
        for (int p = 0; p < PT; p++) {
            if (tx < kt) {
                float v = gmask[(size_t)(b * Pn + p0 + p) * Nn + n0 + tx];
                mt[tx][p] = (__float_as_uint(v) == 0xff800000u) ? 1.0f : v;
            }
        }
        __syncthreads();
#pragma unroll 2
        for (int k = 0; k < kt; k++) {
            float e = Es[k * Hn + tx];
            csum += e;
            unsigned long long e2 = dup2(e);
            const unsigned long long* mr =
                reinterpret_cast<const unsigned long long*>(&mt[k][0]);
#pragma unroll
            for (int j = 0; j < 8; j++) ffma2(acc[j], e2, mr[j]);
        }
        __syncthreads();
    }

    // reuse Es region as transposed [H][PT] tiles (3 * 128*18 floats = 6912 <= 8192)
    float* eq1T  = Es;
    float* lastT = Es + Hn * S2;
    float* aggT  = Es + 2 * Hn * S2;

    meanv[tx] = csum * (1.0f / Nn);
    const float invN = 1.0f / Nn;
#pragma unroll
    for (int j = 0; j < 8; j++) {
        float2 f = unpk(acc[j]);
        aggT[tx * S2 + 2 * j]     = f.x * invN;
        aggT[tx * S2 + 2 * j + 1] = f.y * invN;
    }
#pragma unroll
    for (int p = 0; p < PT; p++) {
        eq1T[tx * S2 + p] = encq1[(size_t)(b * Pn + p0 + p) * Hn + tx];
        int ln = lastn[b * Pn + p0 + p];
        lastT[tx * S2 + p] = emb[(size_t)(b * Nn + ln) * Hn + tx];
    }
    __syncthreads();

    // q_graph for this h
    float qg = 0.f;
#pragma unroll 4
    for (int k = 0; k < Hn; k++) qg = fmaf(meanv[k], Wg[k * Hn + tx], qg);

    // fused projections: q_first + q_last + q_visited
    unsigned long long accp[8];
#pragma unroll
    for (int j = 0; j < 8; j++) accp[j] = 0ull;
#pragma unroll 2
    for (int k = 0; k < Hn; k++) {
        unsigned long long wf2 = dup2(Wf[k * Hn + tx]);
        unsigned long long wl2 = dup2(Wl[k * Hn + tx]);
        unsigned long long wv2 = dup2(Wv[k * Hn + tx]);
        const unsigned long long* e1 = reinterpret_cast<const unsigned long long*>(&eq1T[k * S2]);
        const unsigned long long* l1 = reinterpret_cast<const unsigned long long*>(&lastT[k * S2]);
        const unsigned long long* a1 = reinterpret_cast<const unsigned long long*>(&aggT[k * S2]);
#pragma unroll
        for (int j = 0; j < 8; j++) {
            ffma2(accp[j], wf2, e1[j]);
            ffma2(accp[j], wl2, l1[j]);
            ffma2(accp[j], wv2, a1[j]);
        }
    }

    const float wload_h = Wload[tx];
    const float bl = bload[tx];
#pragma unroll
    for (int j = 0; j < 8; j++) {
        float2 f = unpk(accp[j]);
        int p = 2 * j;
        float v0 = f.x + qg + bl + loadv[b * Pn + p0 + p] * wload_h;
        g_fq[(size_t)(b * Pn + p0 + p) * Hn + tx] = v0;
        float v1 = f.y + qg + bl + loadv[b * Pn + p0 + p + 1] * wload_h;
        g_fq[(size_t)(b * Pn + p0 + p + 1) * Hn + tx] = v1;
    }
}

// =====================================================================
// Kernel 2: score GEMM + distance gather + tanh clip + mask  -> logits
// =====================================================================
__global__ __launch_bounds__(128) void k_score(
    const float* __restrict__ dists,  // [B,N,N]
    const float* __restrict__ emb,    // [B,N,H]
    const int*   __restrict__ lastn,  // [B,P]
    const float* __restrict__ gmask,  // [B,P,N]
    float* __restrict__ out)          // [B,P,N]
{
    const int b  = blockIdx.x >> 2;
    const int p0 = (blockIdx.x & 3) * PT;
    const int tx = threadIdx.x;

    __shared__ __align__(16) float EsT[Hn * NT2];  // transposed E chunk
    __shared__ __align__(16) float fqT[Hn * S2];   // transposed final_q tile
    __shared__ int lns[PT];

#pragma unroll
    for (int p = 0; p < PT; p++)
        fqT[tx * S2 + p] = g_fq[(size_t)(b * Pn + p0 + p) * Hn + tx];
    if (tx < PT) lns[tx] = lastn[b * Pn + p0 + tx];

    const int g = tx >> 6;   // p-half selector
    const int n = tx & 63;   // column within chunk

    for (int n0 = 0; n0 < Nn; n0 += NT) {
        const int nt = min(NT, Nn - n0);
        // stage E chunk transposed: EsT[h][n]
        const float4* eb = reinterpret_cast<const float4*>(emb + (size_t)(b * Nn + n0) * Hn);
        for (int id = tx; id < nt * 32; id += 128) {
            int r = id >> 5, c = id & 31;
            float4 v = eb[id];
            EsT[(4 * c + 0) * NT2 + r] = v.x;
            EsT[(4 * c + 1) * NT2 + r] = v.y;
            EsT[(4 * c + 2) * NT2 + r] = v.z;
            EsT[(4 * c + 3) * NT2 + r] = v.w;
        }
        __syncthreads();

        if (n < nt) {
            unsigned long long acc[4] = {0ull, 0ull, 0ull, 0ull};
#pragma unroll 4
            for (int h = 0; h < Hn; h++) {
                unsigned long long e2 = dup2(EsT[h * NT2 + n]);
                const unsigned long long* fr =
                    reinterpret_cast<const unsigned long long*>(&fqT[h * S2 + 8 * g]);
                ffma2(acc[0], e2, fr[0]);
                ffma2(acc[1], e2, fr[1]);
                ffma2(acc[2], e2, fr[2]);
                ffma2(acc[3], e2, fr[3]);
            }
#pragma unroll
            for (int j = 0; j < 4; j++) {
                float2 f = unpk(acc[j]);
#pragma unroll
                for (int u = 0; u < 2; u++) {
                    float s  = u ? f.y : f.x;
                    int   pp = 8 * g + 2 * j + u;
                    float d  = dists[((size_t)b * Nn + lns[pp]) * Nn + n0 + n];
                    float t  = 10.0f * tanhf(s * 0.08838834764831845f
                                             - d * 0.7071067811865476f);
                    float mv = gmask[(size_t)(b * Pn + p0 + pp) * Nn + n0 + n];
                    t += (__float_as_uint(mv) == 0xff800000u) ? -1e8f : mv;
                    out[(size_t)(b * Pn + p0 + pp) * Nn + n0 + n] = t;
                }
            }
        }
        __syncthreads();
    }
}

// =====================================================================
// Kernel 3: row softmax over N (in place on out)
// =====================================================================
__global__ __launch_bounds__(256) void k_softmax(float* __restrict__ out) {
    __shared__ float buf[Nn];
    __shared__ float red[33];
    const int tx = threadIdx.x;
    float* r = out + (size_t)blockIdx.x * Nn;

    float mx = -3.4e38f;
    for (int i = tx; i < Nn; i += 256) {
        float v = r[i];
        buf[i] = v;
        mx = fmaxf(mx, v);
    }
#pragma unroll
    for (int o = 16; o > 0; o >>= 1) mx = fmaxf(mx, __shfl_xor_sync(0xffffffffu, mx, o));
    if ((tx & 31) == 0) red[tx >> 5] = mx;
    __syncthreads();
    if (tx == 0) {
        float m = red[0];
        for (int w = 1; w < 8; w++) m = fmaxf(m, red[w]);
        red[32] = m;
    }
    __syncthreads();
    mx = red[32];

    float s = 0.f;
    for (int i = tx; i < Nn; i += 256) {
        float e = __expf(buf[i] - mx);
        buf[i] = e;
        s += e;
    }
#pragma unroll
    for (int o = 16; o > 0; o >>= 1) s += __shfl_xor_sync(0xffffffffu, s, o);
    if ((tx & 31) == 0) red[tx >> 5] = s;
    __syncthreads();
    if (tx == 0) {
        float t = 0.f;
        for (int w = 0; w < 8; w++) t += red[w];
        red[32] = 1.0f / t;
    }
    __syncthreads();
    const float inv = red[32];
    for (int i = tx; i < Nn; i += 256) r[i] = buf[i] * inv;
}

// =====================================================================
extern "C" void kernel_launch(void* const* d_in, const int* in_sizes, int n_in,
                              void* d_out, int out_size) {
    (void)in_sizes; (void)n_in; (void)out_size;
    const float* dists  = (const float*)d_in[0];
    const float* emb    = (const float*)d_in[1];
    const float* encq1  = (const float*)d_in[2];
    const int*   lastn  = (const int*)d_in[3];
    const float* loadv  = (const float*)d_in[4];
    const float* gmask  = (const float*)d_in[5];
    const float* Wg     = (const float*)d_in[6];
    const float* Wf     = (const float*)d_in[7];
    const float* Wl     = (const float*)d_in[8];
    const float* Wv     = (const float*)d_in[9];
    const float* Wload  = (const float*)d_in[10];
    const float* bload  = (const float*)d_in[11];
    float* out = (float*)d_out;

    k_prep<<<Bn * PTB, 128>>>(emb, encq1, lastn, loadv, gmask,
                              Wg, Wf, Wl, Wv, Wload, bload);
    k_score<<<Bn * PTB, 128>>>(dists, emb, lastn, gmask, out);
    k_softmax<<<Bn * Pn, 256>>>(out);
}

// round 4
// speedup vs baseline: 1.1197x; 1.1197x over previous
#include <cuda_runtime.h>
#include <math.h>

#define Bn 64
#define Pn 64
#define Nn 1000
#define Hn 128
#define PT 16            // p-tile per k_prep/k_score block
#define PTB (Pn / PT)    // 4
#define NG 250           // n-range per group inside k_prep block (4*250 = 1000)
#define KT 16            // staging chunk per group
#define GSTR 2336        // floats per group region in phase A (16*128 + 16*18)
#define NSC 4            // N-split for score kernel
#define NCS 250          // n per score block
#define NT 64            // score staging sub-chunk
#define NT2 66           // padded stride for transposed E tile
#define S2 18            // padded stride for fq tile in k_score

// only scratch: final_q [B,P,H] (2 MB — identical to the known-passing kernel)
__device__ float g_fq[Bn * Pn * Hn];

typedef unsigned long long ull;

// ---- f32x2 packed-FMA helpers ----
__device__ __forceinline__ void ffma2(ull &d, ull a, ull b) {
    asm("fma.rn.f32x2 %0, %1, %2, %0;" : "+l"(d) : "l"(a), "l"(b));
}
__device__ __forceinline__ ull dup2(float x) {
    ull r;
    asm("mov.b64 %0, {%1, %1};" : "=l"(r) : "f"(x));
    return r;
}
__device__ __forceinline__ float2 unpk(ull v) {
    float2 f;
    asm("mov.b64 {%0, %1}, %2;" : "=f"(f.x), "=f"(f.y) : "l"(v));
    return f;
}

// =====================================================================
// Kernel 1: fused prep. grid = B*PTB = 256, block = 512.
// 4 groups of 128 threads split the N-reduction; SMEM tree-reduce; then
// projections (p-quarter per group) -> g_fq.
// =====================================================================
__global__ __launch_bounds__(512) void k_prep(
    const float* __restrict__ emb,    // [B,N,H]
    const float* __restrict__ encq1,  // [B,P,H]
    const int*   __restrict__ lastn,  // [B,P]
    const float* __restrict__ loadv,  // [B,P]
    const float* __restrict__ gmask,  // [B,P,N]
    const float* __restrict__ Wg, const float* __restrict__ Wf,
    const float* __restrict__ Wl, const float* __restrict__ Wv,
    const float* __restrict__ Wload, const float* __restrict__ bload)
{
    const int b   = blockIdx.x >> 2;
    const int p0  = (blockIdx.x & 3) * PT;
    const int tx  = threadIdx.x;
    const int gid = tx >> 7;    // group 0..3 (n-range, later p-quarter)
    const int h   = tx & 127;

    __shared__ __align__(16) float SB[10624];

    // ---------------- Phase A: masked aggregation over group's n-range ---
    float* Es = SB + gid * GSTR;          // [KT][128]
    float* mt = SB + gid * GSTR + 2048;   // [KT][18] transposed mask

    ull acc[8];
#pragma unroll
    for (int j = 0; j < 8; j++) acc[j] = 0ull;
    float csum = 0.f;

    const int nbeg = gid * NG;
    const int msub = h & 15, mp = h >> 4;   // mask staging coords

    for (int c = 0; c < 16; c++) {
        const int n0 = nbeg + c * KT;
        const int kt = min(KT, nbeg + NG - n0);   // 16 except last chunk = 10
        // stage E chunk (contiguous float4)
        const float4* eb  = reinterpret_cast<const float4*>(emb + (size_t)(b * Nn + n0) * Hn);
        float4*       es4 = reinterpret_cast<float4*>(Es);
        for (int id = h; id < kt * 32; id += 128) es4[id] = eb[id];
        // stage mask chunk transposed (-inf -> 1.0)
#pragma unroll
        for (int s = 0; s < 2; s++) {
            int p = mp + 8 * s;
            if (msub < kt) {
                float v = gmask[(size_t)(b * Pn + p0 + p) * Nn + n0 + msub];
                mt[msub * 18 + p] = (__float_as_uint(v) == 0xff800000u) ? 1.0f : v;
            }
        }
        __syncthreads();
#pragma unroll 2
        for (int k = 0; k < kt; k++) {
            float e = Es[k * 128 + h];
            csum += e;
            ull e2 = dup2(e);
            const ull* mr = reinterpret_cast<const ull*>(mt + k * 18);
#pragma unroll
            for (int j = 0; j < 8; j++) ffma2(acc[j], e2, mr[j]);
        }
        __syncthreads();
    }

    // ---------------- Phase B layout (reuses SB) ------------------------
    float* redb  = SB;            // [2][128][17] partial dump (slot stride 2176)
    float* aggT  = SB + 4352;     // [128][16]
    float* eq1T  = SB + 6400;     // [128][16]
    float* lastT = SB + 8448;     // [128][16]
    float* meanv = SB + 10496;    // [128]

    float a16[16];
#pragma unroll
    for (int j = 0; j < 8; j++) {
        float2 f = unpk(acc[j]);
        a16[2 * j] = f.x;
        a16[2 * j + 1] = f.y;
    }

    // step 1: groups 2,3 dump partials; everyone stages eq1/last tiles
    if (gid >= 2) {
        float* dst = redb + (gid - 2) * 2176 + h * 17;
#pragma unroll
        for (int p = 0; p < 16; p++) dst[p] = a16[p];
        dst[16] = csum;
    }
    const int pq = 4 * gid;
#pragma unroll
    for (int j = 0; j < 4; j++) {
        int p = pq + j;
        eq1T[h * 16 + p] = encq1[(size_t)(b * Pn + p0 + p) * Hn + h];
        int ln = lastn[b * Pn + p0 + p];
        lastT[h * 16 + p] = emb[(size_t)(b * Nn + ln) * Hn + h];
    }
    __syncthreads();

    // step 2: groups 0,1 fold in groups 2,3, dump combined
    if (gid < 2) {
        float* slot = redb + gid * 2176 + h * 17;
#pragma unroll
        for (int p = 0; p < 16; p++) a16[p] += slot[p];
        csum += slot[16];
#pragma unroll
        for (int p = 0; p < 16; p++) slot[p] = a16[p];
        slot[16] = csum;
    }
    __syncthreads();

    // step 3: ownership reduce -> aggT (scaled by 1/N), meanv
    {
        const float invN = 1.0f / Nn;
#pragma unroll
        for (int j = 0; j < 4; j++) {
            int p = pq + j;
            aggT[h * 16 + p] = (redb[h * 17 + p] + redb[2176 + h * 17 + p]) * invN;
        }
        if (gid == 0)
            meanv[h] = (redb[h * 17 + 16] + redb[2176 + h * 17 + 16]) * invN;
    }
    __syncthreads();

    // ---------------- projections: thread (gid,h) does p-quarter pq ------
    ull af0 = 0, af1 = 0, al0 = 0, al1 = 0, av0 = 0, av1 = 0;
    float qg = 0.f;
#pragma unroll 4
    for (int k = 0; k < Hn; k++) {
        qg = fmaf(meanv[k], Wg[k * Hn + h], qg);
        ull wf2 = dup2(Wf[k * Hn + h]);
        ull wl2 = dup2(Wl[k * Hn + h]);
        ull wv2 = dup2(Wv[k * Hn + h]);
        const ull* e1 = reinterpret_cast<const ull*>(eq1T  + k * 16 + pq);
        const ull* l1 = reinterpret_cast<const ull*>(lastT + k * 16 + pq);
        const ull* a1 = reinterpret_cast<const ull*>(aggT  + k * 16 + pq);
        ffma2(af0, wf2, e1[0]); ffma2(af1, wf2, e1[1]);
        ffma2(al0, wl2, l1[0]); ffma2(al1, wl2, l1[1]);
        ffma2(av0, wv2, a1[0]); ffma2(av1, wv2, a1[1]);
    }

    const float wload_h = Wload[h];
    const float bl = bload[h];
    float2 f0 = unpk(af0), f1 = unpk(af1);
    float2 g0 = unpk(al0), g1 = unpk(al1);
    float2 v0 = unpk(av0), v1 = unpk(av1);
    const int pb = b * Pn + p0 + pq;
    g_fq[(size_t)(pb + 0) * Hn + h] = f0.x + g0.x + v0.x + qg + bl + loadv[pb + 0] * wload_h;
    g_fq[(size_t)(pb + 1) * Hn + h] = f0.y + g0.y + v0.y + qg + bl + loadv[pb + 1] * wload_h;
    g_fq[(size_t)(pb + 2) * Hn + h] = f1.x + g1.x + v1.x + qg + bl + loadv[pb + 2] * wload_h;
    g_fq[(size_t)(pb + 3) * Hn + h] = f1.y + g1.y + v1.y + qg + bl + loadv[pb + 3] * wload_h;
}

// =====================================================================
// Kernel 2: score GEMM + distance gather + tanh clip + mask -> logits
// grid = B * PTB * NSC = 1024, block = 128
// =====================================================================
__global__ __launch_bounds__(128) void k_score(
    const float* __restrict__ dists,
    const float* __restrict__ emb,
    const int*   __restrict__ lastn,
    const float* __restrict__ gmask,
    float* __restrict__ out)
{
    const int sc = blockIdx.x & (NSC - 1);
    const int pt = (blockIdx.x >> 2) & (PTB - 1);
    const int b  = blockIdx.x >> 4;
    const int p0 = pt * PT;
    const int tx = threadIdx.x;

    const int nbeg = sc * NCS;
    const int nend = nbeg + NCS;

    __shared__ __align__(16) float EsT[Hn * NT2];
    __shared__ __align__(16) float fqT[Hn * S2];
    __shared__ int lns[PT];

#pragma unroll
    for (int p = 0; p < PT; p++)
        fqT[tx * S2 + p] = g_fq[(size_t)(b * Pn + p0 + p) * Hn + tx];
    if (tx < PT) lns[tx] = lastn[b * Pn + p0 + tx];

    const int g = tx >> 6;
    const int n = tx & 63;

    for (int n0 = nbeg; n0 < nend; n0 += NT) {
        const int nt = min(NT, nend - n0);
        const float4* eb = reinterpret_cast<const float4*>(emb + (size_t)(b * Nn + n0) * Hn);
        for (int id = tx; id < nt * 32; id += 128) {
            int r = id >> 5, c = id & 31;
            float4 v = eb[id];
            EsT[(4 * c + 0) * NT2 + r] = v.x;
            EsT[(4 * c + 1) * NT2 + r] = v.y;
            EsT[(4 * c + 2) * NT2 + r] = v.z;
            EsT[(4 * c + 3) * NT2 + r] = v.w;
        }
        __syncthreads();

        if (n < nt) {
            ull acc[4] = {0ull, 0ull, 0ull, 0ull};
#pragma unroll 4
            for (int hh = 0; hh < Hn; hh++) {
                ull e2 = dup2(EsT[hh * NT2 + n]);
                const ull* fr = reinterpret_cast<const ull*>(&fqT[hh * S2 + 8 * g]);
                ffma2(acc[0], e2, fr[0]);
                ffma2(acc[1], e2, fr[1]);
                ffma2(acc[2], e2, fr[2]);
                ffma2(acc[3], e2, fr[3]);
            }
#pragma unroll
            for (int j = 0; j < 4; j++) {
                float2 f = unpk(acc[j]);
#pragma unroll
                for (int u = 0; u < 2; u++) {
                    float s  = u ? f.y : f.x;
                    int   pp = 8 * g + 2 * j + u;
                    float d  = dists[((size_t)b * Nn + lns[pp]) * Nn + n0 + n];
                    float t  = 10.0f * tanhf(s * 0.08838834764831845f
                                             - d * 0.7071067811865476f);
                    float mv = gmask[(size_t)(b * Pn + p0 + pp) * Nn + n0 + n];
                    t += (__float_as_uint(mv) == 0xff800000u) ? -1e8f : mv;
                    out[(size_t)(b * Pn + p0 + pp) * Nn + n0 + n] = t;
                }
            }
        }
        __syncthreads();
    }
}

// =====================================================================
// Kernel 3: row softmax over N (in place on out)
// =====================================================================
__global__ __launch_bounds__(256) void k_softmax(float* __restrict__ out) {
    __shared__ float buf[Nn];
    __shared__ float red[33];
    const int tx = threadIdx.x;
    float* r = out + (size_t)blockIdx.x * Nn;

    float mx = -3.4e38f;
    for (int i = tx; i < Nn; i += 256) {
        float v = r[i];
        buf[i] = v;
        mx = fmaxf(mx, v);
    }
#pragma unroll
    for (int o = 16; o > 0; o >>= 1) mx = fmaxf(mx, __shfl_xor_sync(0xffffffffu, mx, o));
    if ((tx & 31) == 0) red[tx >> 5] = mx;
    __syncthreads();
    if (tx == 0) {
        float m = red[0];
        for (int w = 1; w < 8; w++) m = fmaxf(m, red[w]);
        red[32] = m;
    }
    __syncthreads();
    mx = red[32];

    float s = 0.f;
    for (int i = tx; i < Nn; i += 256) {
        float e = __expf(buf[i] - mx);
        buf[i] = e;
        s += e;
    }
#pragma unroll
    for (int o = 16; o > 0; o >>= 1) s += __shfl_xor_sync(0xffffffffu, s, o);
    if ((tx & 31) == 0) red[tx >> 5] = s;
    __syncthreads();
    if (tx == 0) {
        float t = 0.f;
        for (int w = 0; w < 8; w++) t += red[w];
        red[32] = 1.0f / t;
    }
    __syncthreads();
    const float inv = red[32];
    for (int i = tx; i < Nn; i += 256) r[i] = buf[i] * inv;
}

// =====================================================================
extern "C" void kernel_launch(void* const* d_in, const int* in_sizes, int n_in,
                              void* d_out, int out_size) {
    (void)in_sizes; (void)n_in; (void)out_size;
    const float* dists  = (const float*)d_in[0];
    const float* emb    = (const float*)d_in[1];
    const float* encq1  = (const float*)d_in[2];
    const int*   lastn  = (const int*)d_in[3];
    const float* loadv  = (const float*)d_in[4];
    const float* gmask  = (const float*)d_in[5];
    const float* Wg     = (const float*)d_in[6];
    const float* Wf     = (const float*)d_in[7];
    const float* Wl     = (const float*)d_in[8];
    const float* Wv     = (const float*)d_in[9];
    const float* Wload  = (const float*)d_in[10];
    const float* bload  = (const float*)d_in[11];
    float* out = (float*)d_out;

    k_prep<<<Bn * PTB, 512>>>(emb, encq1, lastn, loadv, gmask,
                              Wg, Wf, Wl, Wv, Wload, bload);
    k_score<<<Bn * PTB * NSC, 128>>>(dists, emb, lastn, gmask, out);
    k_softmax<<<Bn * Pn, 256>>>(out);
}